// round 6
// baseline (speedup 1.0000x reference)
#include <cuda_runtime.h>

#define N_NODES 50000
#define N_EDGES 200000
#define OUTD 32
#define IN_SELF 128
#define EDGE_DIM 16

#define EDGE_BLOCKS 296
#define EDGE_THREADS 512

// Node GEMM: block tile 128 nodes x 32 chans, K=160 in 5 chunks of 32.
// 256 threads; each owns 4 nodes x 4 chans as 2 node-pairs x 4 chans (f32x2).
#define BN 128
#define KB 32
#define BNP 132
#define WDP 68    // w_d row stride: 64 duplicated floats + 4 mid-pad
#define NT 256

__device__ float g_scratch[N_NODES * OUTD + N_NODES];

__device__ __forceinline__ void red_add_v4(float* ptr, float4 v) {
    asm volatile("red.global.add.v4.f32 [%0], {%1, %2, %3, %4};"
                 :: "l"(ptr), "f"(v.x), "f"(v.y), "f"(v.z), "f"(v.w)
                 : "memory");
}

__device__ __forceinline__ void fma2(unsigned long long& d,
                                     unsigned long long a,
                                     unsigned long long b) {
    asm("fma.rn.f32x2 %0, %1, %2, %0;" : "+l"(d) : "l"(a), "l"(b));
}

// ---------------------------------------------------------------------------
// Edge kernel (unchanged, proven): per-block Wsum reduction, 4 edges/warp,
// 8 lanes/edge, 4 channels/lane, RED.128 into agg.
// ---------------------------------------------------------------------------
__global__ void __launch_bounds__(EDGE_THREADS)
edge_kernel(const float* __restrict__ h_neigh,
            const float* __restrict__ edge_features,
            const float* __restrict__ W_edge,
            const float* __restrict__ b_edge,
            const int* __restrict__ src,
            const int* __restrict__ dst) {
    __shared__ __align__(16) float sW[EDGE_DIM * OUTD];
    __shared__ __align__(16) float sb[OUTD];
    {
        int t = threadIdx.x;
        int j = t >> 4, k = t & 15;
        float s = 0.f;
        #pragma unroll
        for (int i = 0; i < OUTD; i++)
            s += W_edge[(i * OUTD + j) * EDGE_DIM + k];
        sW[k * OUTD + j] = s;
        if (t < OUTD) {
            float s2 = 0.f;
            #pragma unroll
            for (int i = 0; i < OUTD; i++)
                s2 += b_edge[i * OUTD + t];
            sb[t] = s2;
        }
    }
    __syncthreads();

    float* g_agg = g_scratch;
    float* g_deg = g_scratch + N_NODES * OUTD;

    const int lane = threadIdx.x & 31;
    const int warp = threadIdx.x >> 5;
    const int g = lane >> 3;
    const int p = lane & 7;
    const int wpb = EDGE_THREADS >> 5;
    const int nwarps = EDGE_BLOCKS * wpb;
    const int NGROUPS = N_EDGES / 4;

    for (int grp = blockIdx.x * wpb + warp; grp < NGROUPS; grp += nwarps) {
        int e0 = grp * 4;
        int e = e0 + g;
        int s = src[e];
        int d = dst[e];

        float2 ef = *reinterpret_cast<const float2*>(
            &edge_features[e0 * EDGE_DIM + lane * 2]);

        float4 acc = *reinterpret_cast<const float4*>(&sb[4 * p]);
        #pragma unroll
        for (int k = 0; k < EDGE_DIM; k++) {
            float ek = __shfl_sync(0xffffffffu, (k & 1) ? ef.y : ef.x, k >> 1, 8);
            float4 w = *reinterpret_cast<const float4*>(&sW[k * OUTD + 4 * p]);
            acc.x = fmaf(ek, w.x, acc.x);
            acc.y = fmaf(ek, w.y, acc.y);
            acc.z = fmaf(ek, w.z, acc.z);
            acc.w = fmaf(ek, w.w, acc.w);
        }

        float4 hv = *reinterpret_cast<const float4*>(&h_neigh[s * OUTD + 4 * p]);
        float4 msg = make_float4(hv.x * acc.x, hv.y * acc.y,
                                 hv.z * acc.z, hv.w * acc.w);
        red_add_v4(&g_agg[d * OUTD + 4 * p], msg);
        if (p == 0) atomicAdd(&g_deg[d], 1.0f);
    }
}

// ---------------------------------------------------------------------------
// Node kernel: R4 geometry + f32x2 inner loop.
//   out[n,c] = relu( X[n,:] . Wc[c,:] ),  X=[h_self | agg/deg], K=160.
// h staged transposed h_s[k][node] (natural node-pairs for f32x2 a-operand);
// w staged DUPLICATED with mid-row pad: col(c) = 2c + 4*(c>=16), so the two
// tc half-reads use disjoint bank sets (conflict-free LDS.128).
// ---------------------------------------------------------------------------
__global__ void __launch_bounds__(NT, 3)
node_kernel(const float* __restrict__ h_self,
            const float* __restrict__ W_self,
            const float* __restrict__ W_neigh,
            float* __restrict__ out) {
    __shared__ __align__(16) float h_s[2][KB][BNP];
    __shared__ __align__(16) float w_d[2][KB][WDP];
    __shared__ float sinv[BN];

    const float* g_agg = g_scratch;
    const float* g_deg = g_scratch + N_NODES * OUTD;

    const int t = threadIdx.x;
    const int nbase = blockIdx.x * BN;
    const int tn = t >> 3;   // 0..31 -> node quad (nodes 4tn..4tn+3)
    const int tc = t & 7;    // 0..7  -> channel quad (chans 4tc..4tc+3)
    const int woff = tc * 8 + (tc & 4);  // padded w_d column base

    // h staging: idx = t + i*NT (0..1023), node = idx>>3, kvec = idx&7
    const int snode = t >> 3;        // +32 per i
    const int skvec = t & 7;
    // w staging: chan = t>>3 (0..31), kvec = t&7
    const int wchan = t >> 3;
    const int wkvec = t & 7;
    const int wcol = 2 * wchan + ((wchan & 16) >> 2); // duplicated, mid-pad

    if (t < BN) {
        int gn = nbase + t;
        sinv[t] = (gn < N_NODES) ? 1.0f / fmaxf(g_deg[gn], 1.0f) : 0.f;
    }

    float4 hreg[4];
    float4 wreg;

    auto load_regs = [&](int kc) {
        #pragma unroll
        for (int i = 0; i < 4; i++) {
            int node = snode + i * (NT >> 3);   // +0,32,64,96
            int gn = nbase + node;
            float4 v = make_float4(0.f, 0.f, 0.f, 0.f);
            if (gn < N_NODES) {
                if (kc < 4) {
                    v = *reinterpret_cast<const float4*>(
                        &h_self[gn * IN_SELF + kc * KB + skvec * 4]);
                } else {
                    v = *reinterpret_cast<const float4*>(
                        &g_agg[gn * OUTD + skvec * 4]);
                    float iv = sinv[node];
                    v.x *= iv; v.y *= iv; v.z *= iv; v.w *= iv;
                }
            }
            hreg[i] = v;
        }
        if (kc < 4)
            wreg = *reinterpret_cast<const float4*>(
                &W_self[wchan * IN_SELF + kc * KB + wkvec * 4]);
        else
            wreg = *reinterpret_cast<const float4*>(
                &W_neigh[wchan * OUTD + wkvec * 4]);
    };

    auto store_smem = [&](int b) {
        #pragma unroll
        for (int i = 0; i < 4; i++) {
            int node = snode + i * (NT >> 3);
            h_s[b][skvec * 4 + 0][node] = hreg[i].x;
            h_s[b][skvec * 4 + 1][node] = hreg[i].y;
            h_s[b][skvec * 4 + 2][node] = hreg[i].z;
            h_s[b][skvec * 4 + 3][node] = hreg[i].w;
        }
        float wv[4] = {wreg.x, wreg.y, wreg.z, wreg.w};
        #pragma unroll
        for (int j = 0; j < 4; j++) {
            float2 dup = make_float2(wv[j], wv[j]);
            *reinterpret_cast<float2*>(&w_d[b][wkvec * 4 + j][wcol]) = dup;
        }
    };

    // acc2[p][c]: p = node pair (nodes 4tn+2p, 4tn+2p+1), c = channel 4tc+c
    unsigned long long acc2[2][4];
    #pragma unroll
    for (int p = 0; p < 2; p++)
        #pragma unroll
        for (int c = 0; c < 4; c++) acc2[p][c] = 0ull;

    load_regs(0);
    __syncthreads();      // sinv visible, smem free
    store_smem(0);
    __syncthreads();

    #pragma unroll
    for (int kc = 0; kc < 5; kc++) {
        int b = kc & 1;
        if (kc < 4) load_regs(kc + 1);
        #pragma unroll
        for (int kk = 0; kk < KB; kk++) {
            // h: 4 node values = 2 natural packed pairs (one LDS.128)
            ulonglong2 hp = *reinterpret_cast<const ulonglong2*>(&h_s[b][kk][tn * 4]);
            // w: 4 duplicated channel pairs (two conflict-free LDS.128)
            ulonglong2 wA = *reinterpret_cast<const ulonglong2*>(&w_d[b][kk][woff]);
            ulonglong2 wB = *reinterpret_cast<const ulonglong2*>(&w_d[b][kk][woff + 4]);

            fma2(acc2[0][0], hp.x, wA.x);
            fma2(acc2[0][1], hp.x, wA.y);
            fma2(acc2[0][2], hp.x, wB.x);
            fma2(acc2[0][3], hp.x, wB.y);
            fma2(acc2[1][0], hp.y, wA.x);
            fma2(acc2[1][1], hp.y, wA.y);
            fma2(acc2[1][2], hp.y, wB.x);
            fma2(acc2[1][3], hp.y, wB.y);
        }
        if (kc < 4) store_smem(1 - b);
        __syncthreads();
    }

    // epilogue: unpack pairs, relu, STG.128 per node
    #pragma unroll
    for (int p = 0; p < 2; p++) {
        float lo[4], hi[4];
        #pragma unroll
        for (int c = 0; c < 4; c++) {
            float2 v = *reinterpret_cast<float2*>(&acc2[p][c]);
            lo[c] = fmaxf(v.x, 0.f);
            hi[c] = fmaxf(v.y, 0.f);
        }
        int gn0 = nbase + tn * 4 + 2 * p;
        if (gn0 < N_NODES)
            *reinterpret_cast<float4*>(&out[gn0 * OUTD + tc * 4]) =
                make_float4(lo[0], lo[1], lo[2], lo[3]);
        if (gn0 + 1 < N_NODES)
            *reinterpret_cast<float4*>(&out[(gn0 + 1) * OUTD + tc * 4]) =
                make_float4(hi[0], hi[1], hi[2], hi[3]);
    }
}

extern "C" void kernel_launch(void* const* d_in, const int* in_sizes, int n_in,
                              void* d_out, int out_size) {
    const float* h_neigh       = (const float*)d_in[0];
    const float* h_self        = (const float*)d_in[1];
    const float* edge_features = (const float*)d_in[2];
    const float* W_edge        = (const float*)d_in[3];
    const float* b_edge        = (const float*)d_in[4];
    const float* W_self        = (const float*)d_in[5];
    const float* W_neigh       = (const float*)d_in[6];
    const int*   src           = (const int*)d_in[7];
    const int*   dst           = (const int*)d_in[8];
    float* out = (float*)d_out;

    void* scratch_ptr = nullptr;
    cudaGetSymbolAddress(&scratch_ptr, g_scratch);
    cudaMemsetAsync(scratch_ptr, 0, sizeof(float) * (N_NODES * OUTD + N_NODES), 0);

    edge_kernel<<<EDGE_BLOCKS, EDGE_THREADS>>>(h_neigh, edge_features,
                                               W_edge, b_edge, src, dst);

    int node_blocks = (N_NODES + BN - 1) / BN;  // 391
    node_kernel<<<node_blocks, NT>>>(h_self, W_self, W_neigh, out);
}

// round 7
// speedup vs baseline: 1.1715x; 1.1715x over previous
#include <cuda_runtime.h>

#define N_NODES 50000
#define N_EDGES 200000
#define OUTD 32
#define IN_SELF 128
#define EDGE_DIM 16

#define EDGE_BLOCKS 296
#define EDGE_THREADS 512

// Node GEMM: block tile 128 nodes x 32 chans, K=160 staged in 5 chunks of 32.
// 256 threads in 2 K-groups of 128; each thread: 8 nodes x 4 chans over half
// the k-steps of each chunk. f32x2 accumulation on node pairs.
#define BN 128
#define KB 32
#define BNP 132
#define NT 256

__device__ float g_scratch[N_NODES * OUTD + N_NODES];

__device__ __forceinline__ void red_add_v4(float* ptr, float4 v) {
    asm volatile("red.global.add.v4.f32 [%0], {%1, %2, %3, %4};"
                 :: "l"(ptr), "f"(v.x), "f"(v.y), "f"(v.z), "f"(v.w)
                 : "memory");
}

__device__ __forceinline__ void fma2(unsigned long long& d,
                                     unsigned long long a,
                                     unsigned long long b) {
    asm("fma.rn.f32x2 %0, %1, %2, %0;" : "+l"(d) : "l"(a), "l"(b));
}

__device__ __forceinline__ unsigned long long packdup(float v) {
    unsigned long long r;
    asm("mov.b64 %0, {%1, %1};" : "=l"(r) : "f"(v));
    return r;
}

// ---------------------------------------------------------------------------
// Edge kernel (unchanged, proven).
// ---------------------------------------------------------------------------
__global__ void __launch_bounds__(EDGE_THREADS)
edge_kernel(const float* __restrict__ h_neigh,
            const float* __restrict__ edge_features,
            const float* __restrict__ W_edge,
            const float* __restrict__ b_edge,
            const int* __restrict__ src,
            const int* __restrict__ dst) {
    __shared__ __align__(16) float sW[EDGE_DIM * OUTD];
    __shared__ __align__(16) float sb[OUTD];
    {
        int t = threadIdx.x;
        int j = t >> 4, k = t & 15;
        float s = 0.f;
        #pragma unroll
        for (int i = 0; i < OUTD; i++)
            s += W_edge[(i * OUTD + j) * EDGE_DIM + k];
        sW[k * OUTD + j] = s;
        if (t < OUTD) {
            float s2 = 0.f;
            #pragma unroll
            for (int i = 0; i < OUTD; i++)
                s2 += b_edge[i * OUTD + t];
            sb[t] = s2;
        }
    }
    __syncthreads();

    float* g_agg = g_scratch;
    float* g_deg = g_scratch + N_NODES * OUTD;

    const int lane = threadIdx.x & 31;
    const int warp = threadIdx.x >> 5;
    const int g = lane >> 3;
    const int p = lane & 7;
    const int wpb = EDGE_THREADS >> 5;
    const int nwarps = EDGE_BLOCKS * wpb;
    const int NGROUPS = N_EDGES / 4;

    for (int grp = blockIdx.x * wpb + warp; grp < NGROUPS; grp += nwarps) {
        int e0 = grp * 4;
        int e = e0 + g;
        int s = src[e];
        int d = dst[e];

        float2 ef = *reinterpret_cast<const float2*>(
            &edge_features[e0 * EDGE_DIM + lane * 2]);

        float4 acc = *reinterpret_cast<const float4*>(&sb[4 * p]);
        #pragma unroll
        for (int k = 0; k < EDGE_DIM; k++) {
            float ek = __shfl_sync(0xffffffffu, (k & 1) ? ef.y : ef.x, k >> 1, 8);
            float4 w = *reinterpret_cast<const float4*>(&sW[k * OUTD + 4 * p]);
            acc.x = fmaf(ek, w.x, acc.x);
            acc.y = fmaf(ek, w.y, acc.y);
            acc.z = fmaf(ek, w.z, acc.z);
            acc.w = fmaf(ek, w.w, acc.w);
        }

        float4 hv = *reinterpret_cast<const float4*>(&h_neigh[s * OUTD + 4 * p]);
        float4 msg = make_float4(hv.x * acc.x, hv.y * acc.y,
                                 hv.z * acc.z, hv.w * acc.w);
        red_add_v4(&g_agg[d * OUTD + 4 * p], msg);
        if (p == 0) atomicAdd(&g_deg[d], 1.0f);
    }
}

// ---------------------------------------------------------------------------
// Node kernel: split-K f32x2 GEMM.
//   out[n,c] = relu( X[n,:] . Wc[c,:] ),  X=[h_self | agg/deg], K=160.
// Staging identical to R4 (proven). Compute: K-group kg = t>>7 handles
// kk in [kg*16, kg*16+16) of each 32-chunk. Epilogue: group-1 partials
// pushed through smem, group-0 reduces + relu + store.
// ---------------------------------------------------------------------------
__global__ void __launch_bounds__(NT, 3)
node_kernel(const float* __restrict__ h_self,
            const float* __restrict__ W_self,
            const float* __restrict__ W_neigh,
            float* __restrict__ out) {
    __shared__ __align__(16) float h_s[2][KB][BNP];
    __shared__ __align__(16) float w_s[2][KB][OUTD];
    __shared__ float sinv[BN];

    const float* g_agg = g_scratch;
    const float* g_deg = g_scratch + N_NODES * OUTD;

    const int t = threadIdx.x;
    const int nbase = blockIdx.x * BN;
    const int kg = t >> 7;          // K-group 0/1
    const int t1 = t & 127;
    const int tn = t1 >> 3;         // 0..15 -> node octet (nodes 8tn..8tn+7)
    const int tc = t1 & 7;          // 0..7  -> channel quad
    const int ko = kg * (KB / 2);   // k-step offset within chunk

    // staging indices (R4 verbatim): idx = t + i*NT, node=idx>>3, kvec=idx&7
    const int snode = t >> 3;
    const int skvec = t & 7;
    const int wchan = t >> 3;
    const int wkvec = t & 7;

    if (t < BN) {
        int gn = nbase + t;
        sinv[t] = (gn < N_NODES) ? 1.0f / fmaxf(g_deg[gn], 1.0f) : 0.f;
    }

    float4 hreg[4];
    float4 wreg;

    auto load_regs = [&](int kc) {
        #pragma unroll
        for (int i = 0; i < 4; i++) {
            int node = snode + i * (NT >> 3);   // +0,32,64,96
            int gn = nbase + node;
            float4 v = make_float4(0.f, 0.f, 0.f, 0.f);
            if (gn < N_NODES) {
                if (kc < 4) {
                    v = *reinterpret_cast<const float4*>(
                        &h_self[gn * IN_SELF + kc * KB + skvec * 4]);
                } else {
                    v = *reinterpret_cast<const float4*>(
                        &g_agg[gn * OUTD + skvec * 4]);
                    float iv = sinv[node];
                    v.x *= iv; v.y *= iv; v.z *= iv; v.w *= iv;
                }
            }
            hreg[i] = v;
        }
        if (kc < 4)
            wreg = *reinterpret_cast<const float4*>(
                &W_self[wchan * IN_SELF + kc * KB + wkvec * 4]);
        else
            wreg = *reinterpret_cast<const float4*>(
                &W_neigh[wchan * OUTD + wkvec * 4]);
    };

    auto store_smem = [&](int b) {
        #pragma unroll
        for (int i = 0; i < 4; i++) {
            int node = snode + i * (NT >> 3);
            h_s[b][skvec * 4 + 0][node] = hreg[i].x;
            h_s[b][skvec * 4 + 1][node] = hreg[i].y;
            h_s[b][skvec * 4 + 2][node] = hreg[i].z;
            h_s[b][skvec * 4 + 3][node] = hreg[i].w;
        }
        w_s[b][wkvec * 4 + 0][wchan] = wreg.x;
        w_s[b][wkvec * 4 + 1][wchan] = wreg.y;
        w_s[b][wkvec * 4 + 2][wchan] = wreg.z;
        w_s[b][wkvec * 4 + 3][wchan] = wreg.w;
    };

    // acc2[p][c]: node pair (8tn+2p, 8tn+2p+1), channel 4tc+c
    unsigned long long acc2[4][4];
    #pragma unroll
    for (int p = 0; p < 4; p++)
        #pragma unroll
        for (int c = 0; c < 4; c++) acc2[p][c] = 0ull;

    load_regs(0);
    __syncthreads();      // sinv visible, smem free
    store_smem(0);
    __syncthreads();

    #pragma unroll
    for (int kc = 0; kc < 5; kc++) {
        int b = kc & 1;
        if (kc < 4) load_regs(kc + 1);
        #pragma unroll
        for (int kk = 0; kk < KB / 2; kk++) {
            int k = kk + ko;
            float4 w = *reinterpret_cast<const float4*>(&w_s[b][k][tc * 4]);
            unsigned long long w0 = packdup(w.x);
            unsigned long long w1 = packdup(w.y);
            unsigned long long w2 = packdup(w.z);
            unsigned long long w3 = packdup(w.w);
            ulonglong2 hA = *reinterpret_cast<const ulonglong2*>(&h_s[b][k][tn * 8]);
            ulonglong2 hB = *reinterpret_cast<const ulonglong2*>(&h_s[b][k][tn * 8 + 4]);

            fma2(acc2[0][0], hA.x, w0);
            fma2(acc2[0][1], hA.x, w1);
            fma2(acc2[0][2], hA.x, w2);
            fma2(acc2[0][3], hA.x, w3);
            fma2(acc2[1][0], hA.y, w0);
            fma2(acc2[1][1], hA.y, w1);
            fma2(acc2[1][2], hA.y, w2);
            fma2(acc2[1][3], hA.y, w3);
            fma2(acc2[2][0], hB.x, w0);
            fma2(acc2[2][1], hB.x, w1);
            fma2(acc2[2][2], hB.x, w2);
            fma2(acc2[2][3], hB.x, w3);
            fma2(acc2[3][0], hB.y, w0);
            fma2(acc2[3][1], hB.y, w1);
            fma2(acc2[3][2], hB.y, w2);
            fma2(acc2[3][3], hB.y, w3);
        }
        if (kc < 4) store_smem(1 - b);
        __syncthreads();
    }

    // ---- cross-group reduction through smem (reuse h_s as [128][16] u64) ----
    unsigned long long* red = reinterpret_cast<unsigned long long*>(h_s);
    if (kg == 1) {
        #pragma unroll
        for (int p = 0; p < 4; p++)
            #pragma unroll
            for (int c = 0; c < 4; c++)
                red[t1 * 16 + p * 4 + c] = acc2[p][c];
    }
    __syncthreads();
    if (kg == 0) {
        #pragma unroll
        for (int p = 0; p < 4; p++) {
            float lo[4], hi[4];
            #pragma unroll
            for (int c = 0; c < 4; c++) {
                float2 a = *reinterpret_cast<float2*>(&acc2[p][c]);
                unsigned long long o = red[t1 * 16 + p * 4 + c];
                float2 bq = *reinterpret_cast<float2*>(&o);
                lo[c] = fmaxf(a.x + bq.x, 0.f);
                hi[c] = fmaxf(a.y + bq.y, 0.f);
            }
            int gn0 = nbase + tn * 8 + 2 * p;
            if (gn0 < N_NODES)
                *reinterpret_cast<float4*>(&out[gn0 * OUTD + tc * 4]) =
                    make_float4(lo[0], lo[1], lo[2], lo[3]);
            if (gn0 + 1 < N_NODES)
                *reinterpret_cast<float4*>(&out[(gn0 + 1) * OUTD + tc * 4]) =
                    make_float4(hi[0], hi[1], hi[2], hi[3]);
        }
    }
}

extern "C" void kernel_launch(void* const* d_in, const int* in_sizes, int n_in,
                              void* d_out, int out_size) {
    const float* h_neigh       = (const float*)d_in[0];
    const float* h_self        = (const float*)d_in[1];
    const float* edge_features = (const float*)d_in[2];
    const float* W_edge        = (const float*)d_in[3];
    const float* b_edge        = (const float*)d_in[4];
    const float* W_self        = (const float*)d_in[5];
    const float* W_neigh       = (const float*)d_in[6];
    const int*   src           = (const int*)d_in[7];
    const int*   dst           = (const int*)d_in[8];
    float* out = (float*)d_out;

    void* scratch_ptr = nullptr;
    cudaGetSymbolAddress(&scratch_ptr, g_scratch);
    cudaMemsetAsync(scratch_ptr, 0, sizeof(float) * (N_NODES * OUTD + N_NODES), 0);

    edge_kernel<<<EDGE_BLOCKS, EDGE_THREADS>>>(h_neigh, edge_features,
                                               W_edge, b_edge, src, dst);

    int node_blocks = (N_NODES + BN - 1) / BN;  // 391
    node_kernel<<<node_blocks, NT>>>(h_self, W_self, W_neigh, out);
}